// round 1
// baseline (speedup 1.0000x reference)
#include <cuda_runtime.h>
#include <cuda_bf16.h>
#include <cfloat>
#include <cstdint>

// Problem constants
#define HIDDEN   1024
#define NUM_HEADS 16
#define HEAD_DIM  64
#define BATCH     32
#define PREV_LEN  4095
#define SEQ       4096           // PREV_LEN + 1
#define SCALING   0.125f         // HEAD_DIM^-0.5

// Scratch (device globals; no allocation allowed)
__device__ float g_q[BATCH * HIDDEN];
__device__ float g_k[BATCH * HIDDEN];
__device__ float g_v[BATCH * HIDDEN];
__device__ float g_attn[BATCH * HIDDEN];

// ---------------------------------------------------------------------------
// GEMM: out[i,j] = (sum_k X[i,k] * W[j,k] + bias[j]) * scale
//   i < 32, j < 1024, k < 1024.  X row-major (32x1024), W row-major (1024x1024).
// Layout: X staged in smem padded to 1028 floats/row (16B aligned, conflict-free
// float4 reads with lane = i). Each warp computes 2 output columns j with
// uniform (broadcast) W loads -> W streamed exactly once per launch.
// ---------------------------------------------------------------------------
#define XS_STRIDE 1028
#define GEMM_SMEM (32 * XS_STRIDE * 4)

__device__ __forceinline__ void gemm_body(
    const float* __restrict__ X, const float* __restrict__ W,
    const float* __restrict__ bias, float* __restrict__ out,
    float scale, int jblk, float* Xs)
{
    // cooperative load of X (32x1024) into smem
    for (int idx = threadIdx.x; idx < 32 * 1024; idx += 256) {
        int i = idx >> 10, k = idx & 1023;
        Xs[i * XS_STRIDE + k] = X[idx];
    }
    __syncthreads();

    int warp = threadIdx.x >> 5;
    int lane = threadIdx.x & 31;
    int j0 = (jblk * 8 + warp) * 2;    // 2 columns per warp

    const float* W0 = W + (size_t)j0 * 1024;
    const float* W1 = W0 + 1024;
    const float* xr = Xs + lane * XS_STRIDE;

    float a0 = 0.f, a1 = 0.f;
    #pragma unroll 4
    for (int k = 0; k < 1024; k += 4) {
        float4 x4 = *(const float4*)(xr + k);
        float4 w0 = *(const float4*)(W0 + k);   // uniform across warp (broadcast)
        float4 w1 = *(const float4*)(W1 + k);
        a0 += x4.x * w0.x + x4.y * w0.y + x4.z * w0.z + x4.w * w0.w;
        a1 += x4.x * w1.x + x4.y * w1.y + x4.z * w1.z + x4.w * w1.w;
    }
    out[lane * 1024 + j0]     = (a0 + bias[j0])     * scale;
    out[lane * 1024 + j0 + 1] = (a1 + bias[j0 + 1]) * scale;
}

// Fused q/k/v projection: grid = 192 blocks (64 per projection)
__global__ void qkv_kernel(
    const float* __restrict__ Xq, const float* __restrict__ Xk, const float* __restrict__ Xv,
    const float* __restrict__ Wq, const float* __restrict__ bq,
    const float* __restrict__ Wk, const float* __restrict__ bk,
    const float* __restrict__ Wv, const float* __restrict__ bv,
    float* __restrict__ oq, float* __restrict__ ok, float* __restrict__ ov)
{
    extern __shared__ float Xs[];
    int p    = blockIdx.x >> 6;
    int jblk = blockIdx.x & 63;
    if (p == 0)      gemm_body(Xq, Wq, bq, oq, SCALING, jblk, Xs);
    else if (p == 1) gemm_body(Xk, Wk, bk, ok, 1.0f,    jblk, Xs);
    else             gemm_body(Xv, Wv, bv, ov, 1.0f,    jblk, Xs);
}

// Output projection: grid = 64 blocks
__global__ void oproj_kernel(
    const float* __restrict__ X, const float* __restrict__ W,
    const float* __restrict__ bias, float* __restrict__ out)
{
    extern __shared__ float Xs[];
    gemm_body(X, W, bias, out, 1.0f, blockIdx.x, Xs);
}

// ---------------------------------------------------------------------------
// Attention: one block per (batch, head) pair, 8 warps. Each warp does an
// online-softmax pass over positions s = warp, warp+8, ... < 4095. Lane d
// owns dims {2d, 2d+1} as float2 -> each position is a coalesced 256 B read
// of K and of V. Warp 7 appends the fresh (k,v) at s = 4095. 8-way combine
// through shared memory at the end.
// ---------------------------------------------------------------------------
__global__ __launch_bounds__(256) void attn_kernel(
    const float* __restrict__ prev_key, const float* __restrict__ prev_value,
    const int*  __restrict__ order,     const int* __restrict__ mask)
{
    __shared__ float s_mask[SEQ];        // premultiplied FLT_MAX * mask
    __shared__ float sm[8], sl[8];
    __shared__ float sacc[8 * HEAD_DIM];

    int tid  = threadIdx.x;
    int warp = tid >> 5;
    int lane = tid & 31;

    int n = blockIdx.x;                  // 0..511
    int b = n >> 4;
    int h = n & 15;

    for (int idx = tid; idx < SEQ; idx += 256)
        s_mask[idx] = FLT_MAX * (float)mask[idx];
    __syncthreads();

    int ob = order[b];
    size_t cache_base = ((size_t)(ob * NUM_HEADS + h)) * PREV_LEN * HEAD_DIM;
    const float* Kc = prev_key   + cache_base;
    const float* Vc = prev_value + cache_base;

    int qbase = b * HIDDEN + h * HEAD_DIM;
    float2 q2 = *(const float2*)(g_q + qbase + 2 * lane);   // already scaled

    float m = -FLT_MAX, l = 0.f;
    float2 acc = make_float2(0.f, 0.f);

    const float* kp = Kc + (size_t)warp * HEAD_DIM + 2 * lane;
    const float* vp = Vc + (size_t)warp * HEAD_DIM + 2 * lane;

    #pragma unroll 2
    for (int s = warp; s < PREV_LEN; s += 8) {
        float2 k2 = *(const float2*)kp;
        float2 v2 = *(const float2*)vp;
        kp += 8 * HEAD_DIM;
        vp += 8 * HEAD_DIM;

        float p = q2.x * k2.x + q2.y * k2.y;
        p += __shfl_xor_sync(0xffffffffu, p, 16);
        p += __shfl_xor_sync(0xffffffffu, p, 8);
        p += __shfl_xor_sync(0xffffffffu, p, 4);
        p += __shfl_xor_sync(0xffffffffu, p, 2);
        p += __shfl_xor_sync(0xffffffffu, p, 1);

        float score = p - s_mask[s];
        float nm = fmaxf(m, score);
        float es = __expf(m - nm);
        float w  = __expf(score - nm);
        l = l * es + w;
        acc.x = acc.x * es + w * v2.x;
        acc.y = acc.y * es + w * v2.y;
        m = nm;
    }

    // fresh position s = 4095 (uses un-reordered batch index b)
    if (warp == 7) {
        float2 k2 = *(const float2*)(g_k + qbase + 2 * lane);
        float2 v2 = *(const float2*)(g_v + qbase + 2 * lane);
        float p = q2.x * k2.x + q2.y * k2.y;
        p += __shfl_xor_sync(0xffffffffu, p, 16);
        p += __shfl_xor_sync(0xffffffffu, p, 8);
        p += __shfl_xor_sync(0xffffffffu, p, 4);
        p += __shfl_xor_sync(0xffffffffu, p, 2);
        p += __shfl_xor_sync(0xffffffffu, p, 1);
        float score = p - s_mask[PREV_LEN];
        float nm = fmaxf(m, score);
        float es = __expf(m - nm);
        float w  = __expf(score - nm);
        l = l * es + w;
        acc.x = acc.x * es + w * v2.x;
        acc.y = acc.y * es + w * v2.y;
        m = nm;
    }

    sacc[warp * HEAD_DIM + 2 * lane]     = acc.x;
    sacc[warp * HEAD_DIM + 2 * lane + 1] = acc.y;
    if (lane == 0) { sm[warp] = m; sl[warp] = l; }
    __syncthreads();

    if (tid < HEAD_DIM) {
        float M = sm[0];
        #pragma unroll
        for (int w = 1; w < 8; w++) M = fmaxf(M, sm[w]);
        float L = 0.f, A = 0.f;
        #pragma unroll
        for (int w = 0; w < 8; w++) {
            float f = __expf(sm[w] - M);
            L += sl[w] * f;
            A += sacc[w * HEAD_DIM + tid] * f;
        }
        g_attn[qbase + tid] = A / L;
    }
}

// ---------------------------------------------------------------------------
extern "C" void kernel_launch(void* const* d_in, const int* in_sizes, int n_in,
                              void* d_out, int out_size)
{
    const float* qin  = (const float*)d_in[0];
    const float* kin  = (const float*)d_in[1];
    const float* vin  = (const float*)d_in[2];
    const int*   mask = (const int*)  d_in[3];
    const int*   ord  = (const int*)  d_in[4];
    const float* pk   = (const float*)d_in[5];
    const float* pv   = (const float*)d_in[6];
    const float* Wq   = (const float*)d_in[7];
    const float* bq   = (const float*)d_in[8];
    const float* Wk   = (const float*)d_in[9];
    const float* bk   = (const float*)d_in[10];
    const float* Wv   = (const float*)d_in[11];
    const float* bv   = (const float*)d_in[12];
    const float* Wo   = (const float*)d_in[13];
    const float* bo   = (const float*)d_in[14];
    float* out = (float*)d_out;

    float *gq, *gk, *gv, *ga;
    cudaGetSymbolAddress((void**)&gq, g_q);
    cudaGetSymbolAddress((void**)&gk, g_k);
    cudaGetSymbolAddress((void**)&gv, g_v);
    cudaGetSymbolAddress((void**)&ga, g_attn);

    cudaFuncSetAttribute(qkv_kernel,  cudaFuncAttributeMaxDynamicSharedMemorySize, GEMM_SMEM);
    cudaFuncSetAttribute(oproj_kernel, cudaFuncAttributeMaxDynamicSharedMemorySize, GEMM_SMEM);

    qkv_kernel<<<192, 256, GEMM_SMEM>>>(qin, kin, vin, Wq, bq, Wk, bk, Wv, bv, gq, gk, gv);
    attn_kernel<<<512, 256>>>(pk, pv, ord, mask);
    oproj_kernel<<<64, 256, GEMM_SMEM>>>(ga, Wo, bo, out);
}

// round 2
// speedup vs baseline: 2.3862x; 2.3862x over previous
#include <cuda_runtime.h>
#include <cuda_bf16.h>
#include <cfloat>
#include <cstdint>

#define HIDDEN    1024
#define NUM_HEADS 16
#define HEAD_DIM  64
#define BATCH     32
#define PREV_LEN  4095
#define SEQ       4096
#define SCALING   0.125f

__device__ float g_q[BATCH * HIDDEN];
__device__ float g_k[BATCH * HIDDEN];
__device__ float g_v[BATCH * HIDDEN];
__device__ float g_attn[BATCH * HIDDEN];

// ---------------------------------------------------------------------------
// GEMM: out[i,j] = (sum_k X[i,k] * W[j,k] + bias[j]) * scale, i<32, j<1024.
// X (32x1024) staged in smem. Each warp computes 2 columns with COALESCED
// W loads (lanes cover 128 consecutive floats as float4). 32 per-row
// accumulators live in registers; a distributed butterfly reduce leaves
// lane l holding the finished sum for row i=l.
// ---------------------------------------------------------------------------
#define GEMM_SMEM (32 * 1024 * 4)

__device__ __forceinline__ float dot4(float4 a, float4 b) {
    return a.x*b.x + a.y*b.y + a.z*b.z + a.w*b.w;
}

__device__ __forceinline__ void gemm_body(
    const float* __restrict__ X, const float* __restrict__ W,
    const float* __restrict__ bias, float* __restrict__ out,
    float scale, int jblk, float* Xs)
{
    // stage X: 32x1024 floats, coalesced float4 copy
    {
        const float4* X4 = (const float4*)X;
        float4* Xs4 = (float4*)Xs;
        for (int idx = threadIdx.x; idx < 32 * 1024 / 4; idx += 256)
            Xs4[idx] = X4[idx];
    }
    __syncthreads();

    int warp = threadIdx.x >> 5;
    int lane = threadIdx.x & 31;
    int j0 = (jblk * 8 + warp) * 2;

    const float* Wa = W + (size_t)j0 * 1024;
    const float* Wb = Wa + 1024;

    float va[32], vb[32];
    #pragma unroll
    for (int i = 0; i < 32; i++) { va[i] = 0.f; vb[i] = 0.f; }

    // double-buffered coalesced W loads
    float4 wa = *(const float4*)(Wa + lane * 4);
    float4 wb = *(const float4*)(Wb + lane * 4);

    #pragma unroll
    for (int it = 0; it < 8; it++) {
        int k0 = it * 128 + lane * 4;
        float4 ca = wa, cb = wb;
        if (it < 7) {
            wa = *(const float4*)(Wa + k0 + 128);
            wb = *(const float4*)(Wb + k0 + 128);
        }
        const float* xb = Xs + k0;
        #pragma unroll
        for (int i = 0; i < 32; i++) {
            float4 x4 = *(const float4*)(xb + (i << 10));
            va[i] += dot4(x4, ca);
            vb[i] += dot4(x4, cb);
        }
    }

    // distributed tree reduce: after this, va[0]/vb[0] at lane l hold the
    // complete sums for row i = l.
    #pragma unroll
    for (int off = 16; off; off >>= 1) {
        #pragma unroll
        for (int i = 0; i < off; i++) {
            bool hi = (lane & off) != 0;
            float za = hi ? va[i] : va[i + off];
            float zb = hi ? vb[i] : vb[i + off];
            za = __shfl_xor_sync(0xffffffffu, za, off);
            zb = __shfl_xor_sync(0xffffffffu, zb, off);
            va[i] = (hi ? va[i + off] : va[i]) + za;
            vb[i] = (hi ? vb[i + off] : vb[i]) + zb;
        }
    }

    out[lane * 1024 + j0]     = (va[0] + bias[j0])     * scale;
    out[lane * 1024 + j0 + 1] = (vb[0] + bias[j0 + 1]) * scale;
}

__global__ __launch_bounds__(256) void qkv_kernel(
    const float* __restrict__ Xq, const float* __restrict__ Xk, const float* __restrict__ Xv,
    const float* __restrict__ Wq, const float* __restrict__ bq,
    const float* __restrict__ Wk, const float* __restrict__ bk,
    const float* __restrict__ Wv, const float* __restrict__ bv,
    float* __restrict__ oq, float* __restrict__ ok, float* __restrict__ ov)
{
    extern __shared__ float Xs[];
    int p    = blockIdx.x >> 6;
    int jblk = blockIdx.x & 63;
    if (p == 0)      gemm_body(Xq, Wq, bq, oq, SCALING, jblk, Xs);
    else if (p == 1) gemm_body(Xk, Wk, bk, ok, 1.0f,    jblk, Xs);
    else             gemm_body(Xv, Wv, bv, ov, 1.0f,    jblk, Xs);
}

__global__ __launch_bounds__(256) void oproj_kernel(
    const float* __restrict__ X, const float* __restrict__ W,
    const float* __restrict__ bias, float* __restrict__ out)
{
    extern __shared__ float Xs[];
    gemm_body(X, W, bias, out, 1.0f, blockIdx.x, Xs);
}

// ---------------------------------------------------------------------------
// Attention: block per (batch, head). 16 half-warps; half-warp hw handles
// positions s = hw + 16*it. Lane sl owns dims [4*sl, 4*sl+4) as float4 ->
// LDG.128, 256B per position. Dot reduced with 4 intra-half shuffles.
// Online softmax per half-warp; 16-way smem combine at the end.
// ---------------------------------------------------------------------------
__global__ __launch_bounds__(256) void attn_kernel(
    const float* __restrict__ prev_key, const float* __restrict__ prev_value,
    const int*  __restrict__ order,     const int* __restrict__ mask)
{
    __shared__ float s_mask[SEQ];
    __shared__ float s_m[16], s_l[16];
    __shared__ float4 s_acc[16][16];

    int tid = threadIdx.x;
    int hw  = tid >> 4;      // half-warp id 0..15
    int sl  = tid & 15;      // sublane 0..15

    int n = blockIdx.x;
    int b = n >> 4;
    int h = n & 15;

    for (int idx = tid; idx < SEQ; idx += 256)
        s_mask[idx] = FLT_MAX * (float)mask[idx];
    __syncthreads();

    int ob = order[b];
    size_t cache_base = ((size_t)(ob * NUM_HEADS + h)) * PREV_LEN * HEAD_DIM;
    const float* Kc = prev_key   + cache_base;
    const float* Vc = prev_value + cache_base;

    int qbase = b * HIDDEN + h * HEAD_DIM;
    float4 q4 = *(const float4*)(g_q + qbase + sl * 4);   // pre-scaled

    float m = -FLT_MAX, l = 0.f;
    float4 acc = make_float4(0.f, 0.f, 0.f, 0.f);

    #pragma unroll 4
    for (int it = 0; it < 256; it++) {
        int s = (it << 4) + hw;
        const float *kp, *vp;
        if (s < PREV_LEN) {
            kp = Kc + (size_t)s * HEAD_DIM + sl * 4;
            vp = Vc + (size_t)s * HEAD_DIM + sl * 4;
        } else {            // fresh step (only s == 4095)
            kp = g_k + qbase + sl * 4;
            vp = g_v + qbase + sl * 4;
        }
        float4 k4 = *(const float4*)kp;
        float4 v4 = *(const float4*)vp;

        float p = dot4(q4, k4);
        p += __shfl_xor_sync(0xffffffffu, p, 8);
        p += __shfl_xor_sync(0xffffffffu, p, 4);
        p += __shfl_xor_sync(0xffffffffu, p, 2);
        p += __shfl_xor_sync(0xffffffffu, p, 1);

        float score = p - s_mask[s];
        float nm = fmaxf(m, score);
        float es = __expf(m - nm);
        float w  = __expf(score - nm);
        l = l * es + w;
        acc.x = acc.x * es + w * v4.x;
        acc.y = acc.y * es + w * v4.y;
        acc.z = acc.z * es + w * v4.z;
        acc.w = acc.w * es + w * v4.w;
        m = nm;
    }

    s_acc[hw][sl] = acc;
    if (sl == 0) { s_m[hw] = m; s_l[hw] = l; }
    __syncthreads();

    if (tid < HEAD_DIM) {
        float M = s_m[0];
        #pragma unroll
        for (int w = 1; w < 16; w++) M = fmaxf(M, s_m[w]);
        float L = 0.f, A = 0.f;
        #pragma unroll
        for (int w = 0; w < 16; w++) {
            float f = __expf(s_m[w] - M);
            L += s_l[w] * f;
            A += ((const float*)s_acc[w])[tid] * f;
        }
        g_attn[qbase + tid] = A / L;
    }
}

// ---------------------------------------------------------------------------
extern "C" void kernel_launch(void* const* d_in, const int* in_sizes, int n_in,
                              void* d_out, int out_size)
{
    const float* qin  = (const float*)d_in[0];
    const float* kin  = (const float*)d_in[1];
    const float* vin  = (const float*)d_in[2];
    const int*   mask = (const int*)  d_in[3];
    const int*   ord  = (const int*)  d_in[4];
    const float* pk   = (const float*)d_in[5];
    const float* pv   = (const float*)d_in[6];
    const float* Wq   = (const float*)d_in[7];
    const float* bq   = (const float*)d_in[8];
    const float* Wk   = (const float*)d_in[9];
    const float* bk   = (const float*)d_in[10];
    const float* Wv   = (const float*)d_in[11];
    const float* bv   = (const float*)d_in[12];
    const float* Wo   = (const float*)d_in[13];
    const float* bo   = (const float*)d_in[14];
    float* out = (float*)d_out;

    float *gq, *gk, *gv, *ga;
    cudaGetSymbolAddress((void**)&gq, g_q);
    cudaGetSymbolAddress((void**)&gk, g_k);
    cudaGetSymbolAddress((void**)&gv, g_v);
    cudaGetSymbolAddress((void**)&ga, g_attn);

    cudaFuncSetAttribute(qkv_kernel,   cudaFuncAttributeMaxDynamicSharedMemorySize, GEMM_SMEM);
    cudaFuncSetAttribute(oproj_kernel, cudaFuncAttributeMaxDynamicSharedMemorySize, GEMM_SMEM);

    qkv_kernel<<<192, 256, GEMM_SMEM>>>(qin, kin, vin, Wq, bq, Wk, bk, Wv, bv, gq, gk, gv);
    attn_kernel<<<512, 256>>>(pk, pv, ord, mask);
    oproj_kernel<<<64, 256, GEMM_SMEM>>>(ga, Wo, bo, out);
}

// round 3
// speedup vs baseline: 2.6443x; 1.1081x over previous
#include <cuda_runtime.h>
#include <cuda_bf16.h>
#include <cfloat>
#include <cstdint>

#define HIDDEN    1024
#define NUM_HEADS 16
#define HEAD_DIM  64
#define BATCH     32
#define PREV_LEN  4095
#define SEQ       4096
#define SCALING   0.125f

__device__ float g_q[BATCH * HIDDEN];
__device__ float g_k[BATCH * HIDDEN];
__device__ float g_v[BATCH * HIDDEN];
__device__ float g_attn[BATCH * HIDDEN];

__device__ __forceinline__ float dot4(float4 a, float4 b) {
    return a.x*b.x + a.y*b.y + a.z*b.z + a.w*b.w;
}

// ---------------------------------------------------------------------------
// GEMM: out[i,j] = (sum_k X[i,k]*W[j,k] + bias[j]) * scale  (i<32, j<1024)
// Tiling: block = 8 rows x 16 cols, full k=1024. Xs = 8x1024 (32 KB).
// Warp = 2 cols x 8 rows, coalesced double-buffered W loads (512 B/col/chunk),
// 16 accumulators, distributed butterfly reduce -> lanes 0..15 own outputs.
// Grid: qkv 3*4*64 = 768 blocks, oproj 4*64 = 256 blocks.
// ---------------------------------------------------------------------------
#define GEMM_SMEM (8 * 1024 * 4)

__device__ __forceinline__ void gemm_body(
    const float* __restrict__ X, const float* __restrict__ W,
    const float* __restrict__ bias, float* __restrict__ out,
    float scale, int rowtile, int colblk, float* Xs)
{
    int row0 = rowtile * 8;

    // stage 8 rows of X (8x1024 floats) coalesced
    {
        const float4* X4 = (const float4*)(X + row0 * 1024);
        float4* Xs4 = (float4*)Xs;
        for (int idx = threadIdx.x; idx < 8 * 1024 / 4; idx += 256)
            Xs4[idx] = X4[idx];
    }
    __syncthreads();

    int warp = threadIdx.x >> 5;
    int lane = threadIdx.x & 31;
    int j0 = colblk * 16 + warp * 2;

    const float* Wa = W + (size_t)j0 * 1024;
    const float* Wb = Wa + 1024;

    float acc[16];
    #pragma unroll
    for (int i = 0; i < 16; i++) acc[i] = 0.f;

    float4 wa = *(const float4*)(Wa + lane * 4);
    float4 wb = *(const float4*)(Wb + lane * 4);

    #pragma unroll
    for (int it = 0; it < 8; it++) {
        int k0 = it * 128 + lane * 4;
        float4 ca = wa, cb = wb;
        if (it < 7) {
            wa = *(const float4*)(Wa + k0 + 128);
            wb = *(const float4*)(Wb + k0 + 128);
        }
        const float* xb = Xs + k0;
        #pragma unroll
        for (int r = 0; r < 8; r++) {
            float4 x4 = *(const float4*)(xb + (r << 10));
            acc[r]     += dot4(x4, ca);
            acc[8 + r] += dot4(x4, cb);
        }
    }

    // fold lanes 16-31 into 0-15
    #pragma unroll
    for (int i = 0; i < 16; i++)
        acc[i] += __shfl_xor_sync(0xffffffffu, acc[i], 16);
    // distributed reduce: lane l<16 ends with acc[0] = sum for index l
    #pragma unroll
    for (int off = 8; off; off >>= 1) {
        #pragma unroll
        for (int i = 0; i < off; i++) {
            bool hi = (lane & off) != 0;
            float z = hi ? acc[i] : acc[i + off];
            z = __shfl_xor_sync(0xffffffffu, z, off);
            acc[i] = (hi ? acc[i + off] : acc[i]) + z;
        }
    }

    if (lane < 16) {
        int c = lane >> 3, r = lane & 7;
        int j = j0 + c;
        out[(row0 + r) * 1024 + j] = (acc[0] + bias[j]) * scale;
    }
}

__global__ __launch_bounds__(256) void qkv_kernel(
    const float* __restrict__ Xq, const float* __restrict__ Xk, const float* __restrict__ Xv,
    const float* __restrict__ Wq, const float* __restrict__ bq,
    const float* __restrict__ Wk, const float* __restrict__ bk,
    const float* __restrict__ Wv, const float* __restrict__ bv,
    float* __restrict__ oq, float* __restrict__ ok, float* __restrict__ ov)
{
    extern __shared__ float Xs[];
    int blk = blockIdx.x;            // p*256 + rt*64 + cb
    int p   = blk >> 8;
    int rt  = (blk >> 6) & 3;
    int cb  = blk & 63;
    if (p == 0)      gemm_body(Xq, Wq, bq, oq, SCALING, rt, cb, Xs);
    else if (p == 1) gemm_body(Xk, Wk, bk, ok, 1.0f,    rt, cb, Xs);
    else             gemm_body(Xv, Wv, bv, ov, 1.0f,    rt, cb, Xs);
}

__global__ __launch_bounds__(256) void oproj_kernel(
    const float* __restrict__ X, const float* __restrict__ W,
    const float* __restrict__ bias, float* __restrict__ out)
{
    extern __shared__ float Xs[];
    int rt = blockIdx.x >> 6;
    int cb = blockIdx.x & 63;
    gemm_body(X, W, bias, out, 1.0f, rt, cb, Xs);
}

// ---------------------------------------------------------------------------
// Attention (unchanged — measured at ~7.6 TB/s, at the LTS/HBM cap).
// Block per (batch, head); 16 half-warps; lane owns 4 dims as float4.
// ---------------------------------------------------------------------------
__global__ __launch_bounds__(256) void attn_kernel(
    const float* __restrict__ prev_key, const float* __restrict__ prev_value,
    const int*  __restrict__ order,     const int* __restrict__ mask)
{
    __shared__ float s_mask[SEQ];
    __shared__ float s_m[16], s_l[16];
    __shared__ float4 s_acc[16][16];

    int tid = threadIdx.x;
    int hw  = tid >> 4;
    int sl  = tid & 15;

    int n = blockIdx.x;
    int b = n >> 4;
    int h = n & 15;

    for (int idx = tid; idx < SEQ; idx += 256)
        s_mask[idx] = FLT_MAX * (float)mask[idx];
    __syncthreads();

    int ob = order[b];
    size_t cache_base = ((size_t)(ob * NUM_HEADS + h)) * PREV_LEN * HEAD_DIM;
    const float* Kc = prev_key   + cache_base;
    const float* Vc = prev_value + cache_base;

    int qbase = b * HIDDEN + h * HEAD_DIM;
    float4 q4 = *(const float4*)(g_q + qbase + sl * 4);

    float m = -FLT_MAX, l = 0.f;
    float4 acc = make_float4(0.f, 0.f, 0.f, 0.f);

    #pragma unroll 4
    for (int it = 0; it < 256; it++) {
        int s = (it << 4) + hw;
        const float *kp, *vp;
        if (s < PREV_LEN) {
            kp = Kc + (size_t)s * HEAD_DIM + sl * 4;
            vp = Vc + (size_t)s * HEAD_DIM + sl * 4;
        } else {
            kp = g_k + qbase + sl * 4;
            vp = g_v + qbase + sl * 4;
        }
        float4 k4 = *(const float4*)kp;
        float4 v4 = *(const float4*)vp;

        float p = dot4(q4, k4);
        p += __shfl_xor_sync(0xffffffffu, p, 8);
        p += __shfl_xor_sync(0xffffffffu, p, 4);
        p += __shfl_xor_sync(0xffffffffu, p, 2);
        p += __shfl_xor_sync(0xffffffffu, p, 1);

        float score = p - s_mask[s];
        float nm = fmaxf(m, score);
        float es = __expf(m - nm);
        float w  = __expf(score - nm);
        l = l * es + w;
        acc.x = acc.x * es + w * v4.x;
        acc.y = acc.y * es + w * v4.y;
        acc.z = acc.z * es + w * v4.z;
        acc.w = acc.w * es + w * v4.w;
        m = nm;
    }

    s_acc[hw][sl] = acc;
    if (sl == 0) { s_m[hw] = m; s_l[hw] = l; }
    __syncthreads();

    if (tid < HEAD_DIM) {
        float M = s_m[0];
        #pragma unroll
        for (int w = 1; w < 16; w++) M = fmaxf(M, s_m[w]);
        float L = 0.f, A = 0.f;
        #pragma unroll
        for (int w = 0; w < 16; w++) {
            float f = __expf(s_m[w] - M);
            L += s_l[w] * f;
            A += ((const float*)s_acc[w])[tid] * f;
        }
        g_attn[qbase + tid] = A / L;
    }
}

// ---------------------------------------------------------------------------
extern "C" void kernel_launch(void* const* d_in, const int* in_sizes, int n_in,
                              void* d_out, int out_size)
{
    const float* qin  = (const float*)d_in[0];
    const float* kin  = (const float*)d_in[1];
    const float* vin  = (const float*)d_in[2];
    const int*   mask = (const int*)  d_in[3];
    const int*   ord  = (const int*)  d_in[4];
    const float* pk   = (const float*)d_in[5];
    const float* pv   = (const float*)d_in[6];
    const float* Wq   = (const float*)d_in[7];
    const float* bq   = (const float*)d_in[8];
    const float* Wk   = (const float*)d_in[9];
    const float* bk   = (const float*)d_in[10];
    const float* Wv   = (const float*)d_in[11];
    const float* bv   = (const float*)d_in[12];
    const float* Wo   = (const float*)d_in[13];
    const float* bo   = (const float*)d_in[14];
    float* out = (float*)d_out;

    float *gq, *gk, *gv, *ga;
    cudaGetSymbolAddress((void**)&gq, g_q);
    cudaGetSymbolAddress((void**)&gk, g_k);
    cudaGetSymbolAddress((void**)&gv, g_v);
    cudaGetSymbolAddress((void**)&ga, g_attn);

    cudaFuncSetAttribute(qkv_kernel,   cudaFuncAttributeMaxDynamicSharedMemorySize, GEMM_SMEM);
    cudaFuncSetAttribute(oproj_kernel, cudaFuncAttributeMaxDynamicSharedMemorySize, GEMM_SMEM);

    qkv_kernel<<<768, 256, GEMM_SMEM>>>(qin, kin, vin, Wq, bq, Wk, bk, Wv, bv, gq, gk, gv);
    attn_kernel<<<512, 256>>>(pk, pv, ord, mask);
    oproj_kernel<<<256, 256, GEMM_SMEM>>>(ga, Wo, bo, out);
}